// round 1
// baseline (speedup 1.0000x reference)
#include <cuda_runtime.h>
#include <cuda_bf16.h>
#include <math.h>

// Problem constants (match reference_code)
#define BB 1024   // batch
#define TT 1024   // time
#define DD 2      // input dim
#define HH 32     // hidden
// 4*HH = 128 gate rows per layer

// Key simplifications proven from the reference:
//  - hx is zeros for every cell call  -> Wh{l} terms are identically 0
//  - layer 0 has cx = 0               -> cy0 = sig(i)*tanh(g)
//  - only rows n = b*T + (T-1) reach the output (h[:, -1, :] @ Wfc.T + bfc)
// => total surviving work: 1024 tiny per-batch computations (~9 MFLOP).

__device__ __forceinline__ float sigmoidf_(float v) {
    return 1.0f / (1.0f + expf(-v));
}

__global__ __launch_bounds__(256)
void lstm_collapsed_kernel(
    const float* __restrict__ x,
    const float* __restrict__ Wx0, const float* __restrict__ bx0, const float* __restrict__ bh0,
    const float* __restrict__ Wx1, const float* __restrict__ bx1, const float* __restrict__ bh1,
    const float* __restrict__ Wx2, const float* __restrict__ bx2, const float* __restrict__ bh2,
    const float* __restrict__ Wfc, const float* __restrict__ bfc,
    float* __restrict__ out)
{
    // Shared staging. W1t/W2t are TRANSPOSED: [k][row] so the inner-loop
    // access sW[k*128 + gate*32 + lane] is lane-consecutive (bank-conflict free).
    __shared__ float sW0[4 * HH * DD];       // 256   : [row][d], row-major as in gmem
    __shared__ float sW1t[HH * 4 * HH];      // 4096  : [k][row]
    __shared__ float sW2t[HH * 4 * HH];      // 4096  : [k][row]
    __shared__ float sb0[4 * HH], sb1[4 * HH], sb2[4 * HH];  // fused bx+bh
    __shared__ float sWfc[HH];

    const int tid = threadIdx.x;

    for (int i = tid; i < 4 * HH * HH; i += blockDim.x) {
        const int row = i >> 5;       // 0..127
        const int k   = i & 31;       // 0..31
        sW1t[k * 128 + row] = Wx1[i];
        sW2t[k * 128 + row] = Wx2[i];
    }
    for (int i = tid; i < 4 * HH * DD; i += blockDim.x) sW0[i] = Wx0[i];
    for (int i = tid; i < 4 * HH; i += blockDim.x) {
        sb0[i] = bx0[i] + bh0[i];
        sb1[i] = bx1[i] + bh1[i];
        sb2[i] = bx2[i] + bh2[i];
    }
    if (tid < HH) sWfc[tid] = Wfc[tid];
    __syncthreads();

    const int warp = tid >> 5;
    const int lane = tid & 31;
    const int b = blockIdx.x * (blockDim.x >> 5) + warp;   // one warp per batch elem
    if (b >= BB) return;   // grid sized exactly; kept for safety (no syncs below)

    // Only the last timestep of each batch row matters.
    const float* xr = x + ((size_t)b * TT + (TT - 1)) * DD;
    const float x0 = xr[0];
    const float x1 = xr[1];

    // ---- layer 0: gates = x @ Wx0^T + (bx0+bh0); cx = 0 ----
    const float gi0 = sW0[(0 * HH + lane) * DD + 0] * x0 + sW0[(0 * HH + lane) * DD + 1] * x1 + sb0[0 * HH + lane];
    const float gg0 = sW0[(2 * HH + lane) * DD + 0] * x0 + sW0[(2 * HH + lane) * DD + 1] * x1 + sb0[2 * HH + lane];
    const float go0 = sW0[(3 * HH + lane) * DD + 0] * x0 + sW0[(3 * HH + lane) * DD + 1] * x1 + sb0[3 * HH + lane];
    float c = sigmoidf_(gi0) * tanhf(gg0);         // f-gate term vanishes (cx=0)
    float h = sigmoidf_(go0) * tanhf(c);

    // ---- layers 1 & 2: gates = h @ Wx^T + (bx+bh); cx carried forward ----
    #pragma unroll
    for (int layer = 1; layer < 3; layer++) {
        const float* sW = (layer == 1) ? sW1t : sW2t;
        const float* sb = (layer == 1) ? sb1  : sb2;
        float ai = sb[0 * HH + lane];
        float af = sb[1 * HH + lane];
        float ag = sb[2 * HH + lane];
        float ao = sb[3 * HH + lane];
        #pragma unroll
        for (int k = 0; k < HH; k++) {
            const float hk = __shfl_sync(0xffffffffu, h, k);
            const float* w = sW + k * 128;
            ai = fmaf(w[0 * HH + lane], hk, ai);
            af = fmaf(w[1 * HH + lane], hk, af);
            ag = fmaf(w[2 * HH + lane], hk, ag);
            ao = fmaf(w[3 * HH + lane], hk, ao);
        }
        c = c * sigmoidf_(af) + sigmoidf_(ai) * tanhf(ag);
        h = sigmoidf_(ao) * tanhf(c);
    }

    // ---- final FC: out[b] = sum_k h[k]*Wfc[k] + bfc ----
    float p = h * sWfc[lane];
    #pragma unroll
    for (int off = 16; off > 0; off >>= 1)
        p += __shfl_down_sync(0xffffffffu, p, off);
    if (lane == 0) out[b] = p + bfc[0];
}

extern "C" void kernel_launch(void* const* d_in, const int* in_sizes, int n_in,
                              void* d_out, int out_size)
{
    // metadata order: x, Wx0,bx0,Wh0,bh0, Wx1,bx1,Wh1,bh1, Wx2,bx2,Wh2,bh2, Wfc,bfc
    const float* x   = (const float*)d_in[0];
    const float* Wx0 = (const float*)d_in[1];
    const float* bx0 = (const float*)d_in[2];
    // d_in[3] = Wh0 (unused: hx == 0)
    const float* bh0 = (const float*)d_in[4];
    const float* Wx1 = (const float*)d_in[5];
    const float* bx1 = (const float*)d_in[6];
    // d_in[7] = Wh1 (unused)
    const float* bh1 = (const float*)d_in[8];
    const float* Wx2 = (const float*)d_in[9];
    const float* bx2 = (const float*)d_in[10];
    // d_in[11] = Wh2 (unused)
    const float* bh2 = (const float*)d_in[12];
    const float* Wfc = (const float*)d_in[13];
    const float* bfc = (const float*)d_in[14];
    float* out = (float*)d_out;

    const int warps_per_block = 256 / 32;               // 8
    const int blocks = BB / warps_per_block;            // 128
    lstm_collapsed_kernel<<<blocks, 256>>>(
        x, Wx0, bx0, bh0, Wx1, bx1, bh1, Wx2, bx2, bh2, Wfc, bfc, out);
}

// round 2
// speedup vs baseline: 1.2031x; 1.2031x over previous
#include <cuda_runtime.h>
#include <cuda_bf16.h>
#include <math.h>

// Problem constants (match reference_code)
#define BB 1024   // batch
#define TT 1024   // time
#define DD 2      // input dim
#define HH 32     // hidden
#define GR (4*HH) // 128 gate rows per layer
#define WS 129    // padded k-stride for transposed weights (kills bank conflicts)

// Simplifications proven from the reference:
//  - hx == 0 for every cell call  -> Wh{l} terms vanish; bx+bh fuse
//  - layer 0 has cx == 0          -> cy0 = sig(i)*tanh(g)
//  - only rows n = b*T + (T-1) reach the output

__device__ __forceinline__ float fsig(float v) {
    // sigmoid via MUFU ex2 + rcp (err ~1e-6, tolerance is 1e-3)
    float e = __expf(-v);
    return __fdividef(1.0f, 1.0f + e);
}
__device__ __forceinline__ float ftanh(float v) {
    float r;
    asm("tanh.approx.f32 %0, %1;" : "=f"(r) : "f"(v));
    return r;
}

__global__ __launch_bounds__(512)
void lstm_collapsed_kernel(
    const float* __restrict__ x,
    const float* __restrict__ Wx0, const float* __restrict__ bx0, const float* __restrict__ bh0,
    const float* __restrict__ Wx1, const float* __restrict__ bx1, const float* __restrict__ bh1,
    const float* __restrict__ Wx2, const float* __restrict__ bx2, const float* __restrict__ bh2,
    const float* __restrict__ Wfc, const float* __restrict__ bfc,
    float* __restrict__ out)
{
    // Transposed weights, padded stride: sWt[k*WS + row]. Both the staging STS
    // (lanes vary k, fixed row) and hot-loop LDS (lanes vary row, fixed k) hit
    // distinct banks: bank = (k + row) % 32.
    __shared__ float sW1t[HH * WS];          // 4128 floats
    __shared__ float sW2t[HH * WS];
    __shared__ float sW0[GR * DD];           // 256 : [row][d] row-major
    __shared__ float sb0[GR], sb1[GR], sb2[GR];  // fused bx+bh
    __shared__ float sWfc[HH];

    const int tid  = threadIdx.x;
    const int warp = tid >> 5;
    const int lane = tid & 31;
    const int b = blockIdx.x * (blockDim.x >> 5) + warp;   // one warp per batch elem

    // Kick off the scattered per-batch DRAM load of x BEFORE staging, so its
    // ~600-cycle latency hides under the weight staging below.
    const float* xr = x + ((size_t)b * TT + (TT - 1)) * DD;
    const float x0 = xr[0];
    const float x1 = xr[1];

    for (int i = tid; i < GR * HH; i += blockDim.x) {   // 8 iters @512 thr
        const int row = i >> 5;       // 0..127
        const int k   = i & 31;       // 0..31
        sW1t[k * WS + row] = Wx1[i];
        sW2t[k * WS + row] = Wx2[i];
    }
    for (int i = tid; i < GR * DD; i += blockDim.x) sW0[i] = Wx0[i];
    if (tid < GR) {
        sb0[tid] = bx0[tid] + bh0[tid];
        sb1[tid] = bx1[tid] + bh1[tid];
        sb2[tid] = bx2[tid] + bh2[tid];
    }
    if (tid < HH) sWfc[tid] = Wfc[tid];
    __syncthreads();

    // ---- layer 0: gates = x @ Wx0^T + (bx0+bh0); cx = 0 ----
    const float gi0 = fmaf(sW0[(0*HH + lane)*DD + 1], x1, fmaf(sW0[(0*HH + lane)*DD + 0], x0, sb0[0*HH + lane]));
    const float gg0 = fmaf(sW0[(2*HH + lane)*DD + 1], x1, fmaf(sW0[(2*HH + lane)*DD + 0], x0, sb0[2*HH + lane]));
    const float go0 = fmaf(sW0[(3*HH + lane)*DD + 1], x1, fmaf(sW0[(3*HH + lane)*DD + 0], x0, sb0[3*HH + lane]));
    float c = fsig(gi0) * ftanh(gg0);         // f-gate term vanishes (cx=0)
    float h = fsig(go0) * ftanh(c);

    // ---- layers 1 & 2: gates = h @ Wx^T + (bx+bh); cx carried ----
    #pragma unroll
    for (int layer = 1; layer < 3; layer++) {
        const float* sW = (layer == 1) ? sW1t : sW1t + 0;  // placeholder, fixed below
        sW = (layer == 1) ? sW1t : sW2t;
        const float* sb = (layer == 1) ? sb1  : sb2;
        float ai = sb[0*HH + lane];
        float af = sb[1*HH + lane];
        float ag = sb[2*HH + lane];
        float ao = sb[3*HH + lane];
        #pragma unroll
        for (int k = 0; k < HH; k++) {
            const float hk = __shfl_sync(0xffffffffu, h, k);
            const float* w = sW + k * WS;
            ai = fmaf(w[0*HH + lane], hk, ai);
            af = fmaf(w[1*HH + lane], hk, af);
            ag = fmaf(w[2*HH + lane], hk, ag);
            ao = fmaf(w[3*HH + lane], hk, ao);
        }
        c = c * fsig(af) + fsig(ai) * ftanh(ag);
        h = fsig(ao) * ftanh(c);
    }

    // ---- final FC: out[b] = sum_k h[k]*Wfc[k] + bfc ----
    float p = h * sWfc[lane];
    #pragma unroll
    for (int off = 16; off > 0; off >>= 1)
        p += __shfl_down_sync(0xffffffffu, p, off);
    if (lane == 0) out[b] = p + bfc[0];
}

extern "C" void kernel_launch(void* const* d_in, const int* in_sizes, int n_in,
                              void* d_out, int out_size)
{
    // metadata order: x, Wx0,bx0,Wh0,bh0, Wx1,bx1,Wh1,bh1, Wx2,bx2,Wh2,bh2, Wfc,bfc
    const float* x   = (const float*)d_in[0];
    const float* Wx0 = (const float*)d_in[1];
    const float* bx0 = (const float*)d_in[2];
    const float* bh0 = (const float*)d_in[4];   // Wh0 (d_in[3]) unused: hx == 0
    const float* Wx1 = (const float*)d_in[5];
    const float* bx1 = (const float*)d_in[6];
    const float* bh1 = (const float*)d_in[8];   // Wh1 unused
    const float* Wx2 = (const float*)d_in[9];
    const float* bx2 = (const float*)d_in[10];
    const float* bh2 = (const float*)d_in[12];  // Wh2 unused
    const float* Wfc = (const float*)d_in[13];
    const float* bfc = (const float*)d_in[14];
    float* out = (float*)d_out;

    const int threads = 512;                         // 16 warps = 16 batch/block
    const int blocks  = BB / (threads / 32);         // 64
    lstm_collapsed_kernel<<<blocks, threads>>>(
        x, Wx0, bx0, bh0, Wx1, bx1, bh1, Wx2, bx2, bh2, Wfc, bfc, out);
}

// round 3
// speedup vs baseline: 1.2145x; 1.0095x over previous
#include <cuda_runtime.h>
#include <cuda_bf16.h>
#include <math.h>

// Problem constants (match reference_code)
#define BB 1024   // batch
#define TT 1024   // time
#define DD 2      // input dim
#define HH 32     // hidden
#define GR 128    // 4*HH gate rows per layer
#define KS 132    // k-stride (floats) for interleaved transposed weights:
                  // 132*4 bytes % 16 == 0 -> LDS.128 aligned; lane*16B -> conflict-free

// Proven simplifications:
//  - hx == 0 for every cell call  -> Wh{l} terms vanish; bx+bh fuse
//  - layer 0 has cx == 0          -> c0 = sig(i)*tanh(g)
//  - only rows n = b*T + (T-1) reach the output

__device__ __forceinline__ float fsig(float v) {
    return __fdividef(1.0f, 1.0f + __expf(-v));
}
__device__ __forceinline__ float ftanh(float v) {
    float r; asm("tanh.approx.f32 %0, %1;" : "=f"(r) : "f"(v)); return r;
}

// One dense LSTM layer (hx=0 form). Weights in interleaved-transposed smem:
// sWt[k*KS + r*4 + g] = W[g*32 + r][k].  Lane r reads float4 {i,f,g,o} rows.
// h-vector is read from the warp's 32-float smem slab via broadcast LDS.128.
__device__ __forceinline__ void lstm_dense_layer(
    const float* __restrict__ sWt, const float* __restrict__ sb,
    const float* __restrict__ shwarp, int lane, float& h, float& c)
{
    float4 hv[8];
    #pragma unroll
    for (int j = 0; j < 8; j++)
        hv[j] = *reinterpret_cast<const float4*>(shwarp + 4 * j);   // broadcast

    float ai = sb[0 * HH + lane];
    float af = sb[1 * HH + lane];
    float ag = sb[2 * HH + lane];
    float ao = sb[3 * HH + lane];

    #pragma unroll
    for (int j = 0; j < 8; j++) {
        #pragma unroll
        for (int t = 0; t < 4; t++) {
            const int k = 4 * j + t;
            const float hk = (t == 0) ? hv[j].x : (t == 1) ? hv[j].y
                           : (t == 2) ? hv[j].z : hv[j].w;
            const float4 w = *reinterpret_cast<const float4*>(sWt + k * KS + lane * 4);
            ai = fmaf(w.x, hk, ai);
            af = fmaf(w.y, hk, af);
            ag = fmaf(w.z, hk, ag);
            ao = fmaf(w.w, hk, ao);
        }
    }
    c = c * fsig(af) + fsig(ai) * ftanh(ag);
    h = fsig(ao) * ftanh(c);
}

__global__ __launch_bounds__(512)
void lstm_collapsed_kernel(
    const float* __restrict__ x,
    const float* __restrict__ Wx0, const float* __restrict__ bx0, const float* __restrict__ bh0,
    const float* __restrict__ Wx1, const float* __restrict__ bx1, const float* __restrict__ bh1,
    const float* __restrict__ Wx2, const float* __restrict__ bx2, const float* __restrict__ bh2,
    const float* __restrict__ Wfc, const float* __restrict__ bfc,
    float* __restrict__ out)
{
    __shared__ float sW1t[HH * KS];          // 4224 floats, interleaved-transposed
    __shared__ float sW2t[HH * KS];
    __shared__ float sW0[GR * DD];           // [row][d] row-major
    __shared__ float sb0[GR], sb1[GR], sb2[GR];  // fused bx+bh
    __shared__ float sWfc[HH];
    __shared__ float sh[16 * HH];            // per-warp h broadcast slabs

    const int tid  = threadIdx.x;
    const int warp = tid >> 5;
    const int lane = tid & 31;
    const int b = blockIdx.x * (blockDim.x >> 5) + warp;   // one warp per batch elem

    // Scattered per-batch x load issued before staging to hide DRAM latency.
    const float* xr = x + ((size_t)b * TT + (TT - 1)) * DD;
    const float x0 = xr[0];
    const float x1 = xr[1];

    // Stage weights. LDG coalesced; STS is 4-way conflicted but runs once.
    for (int i = tid; i < GR * HH; i += blockDim.x) {     // 8 iters @512
        const int row = i >> 5;           // 0..127
        const int k   = i & 31;           // 0..31
        const int g   = row >> 5;         // gate 0..3
        const int r   = row & 31;         // unit 0..31
        const int a   = k * KS + r * 4 + g;
        sW1t[a] = Wx1[i];
        sW2t[a] = Wx2[i];
    }
    for (int i = tid; i < GR * DD; i += blockDim.x) sW0[i] = Wx0[i];
    if (tid < GR) {
        sb0[tid] = bx0[tid] + bh0[tid];
        sb1[tid] = bx1[tid] + bh1[tid];
        sb2[tid] = bx2[tid] + bh2[tid];
    }
    if (tid < HH) sWfc[tid] = Wfc[tid];
    __syncthreads();

    // ---- layer 0: gates = x @ Wx0^T + (bx0+bh0); cx = 0 ----
    const float2 wi = *reinterpret_cast<const float2*>(sW0 + (0 * HH + lane) * DD);
    const float2 wg = *reinterpret_cast<const float2*>(sW0 + (2 * HH + lane) * DD);
    const float2 wo = *reinterpret_cast<const float2*>(sW0 + (3 * HH + lane) * DD);
    const float gi0 = fmaf(wi.y, x1, fmaf(wi.x, x0, sb0[0 * HH + lane]));
    const float gg0 = fmaf(wg.y, x1, fmaf(wg.x, x0, sb0[2 * HH + lane]));
    const float go0 = fmaf(wo.y, x1, fmaf(wo.x, x0, sb0[3 * HH + lane]));
    float c = fsig(gi0) * ftanh(gg0);         // f-gate term vanishes (cx=0)
    float h = fsig(go0) * ftanh(c);

    float* shw = sh + warp * HH;

    // ---- layer 1 ----
    shw[lane] = h;
    __syncwarp();
    lstm_dense_layer(sW1t, sb1, shw, lane, h, c);

    // ---- layer 2 ----
    __syncwarp();                  // all lanes done reading layer-1 slab
    shw[lane] = h;
    __syncwarp();
    lstm_dense_layer(sW2t, sb2, shw, lane, h, c);

    // ---- final FC: out[b] = sum_k h[k]*Wfc[k] + bfc ----
    float p = h * sWfc[lane];
    #pragma unroll
    for (int off = 16; off > 0; off >>= 1)
        p += __shfl_down_sync(0xffffffffu, p, off);
    if (lane == 0) out[b] = p + bfc[0];
}

extern "C" void kernel_launch(void* const* d_in, const int* in_sizes, int n_in,
                              void* d_out, int out_size)
{
    // metadata order: x, Wx0,bx0,Wh0,bh0, Wx1,bx1,Wh1,bh1, Wx2,bx2,Wh2,bh2, Wfc,bfc
    const float* x   = (const float*)d_in[0];
    const float* Wx0 = (const float*)d_in[1];
    const float* bx0 = (const float*)d_in[2];
    const float* bh0 = (const float*)d_in[4];   // Wh0 (d_in[3]) unused: hx == 0
    const float* Wx1 = (const float*)d_in[5];
    const float* bx1 = (const float*)d_in[6];
    const float* bh1 = (const float*)d_in[8];   // Wh1 unused
    const float* Wx2 = (const float*)d_in[9];
    const float* bx2 = (const float*)d_in[10];
    const float* bh2 = (const float*)d_in[12];  // Wh2 unused
    const float* Wfc = (const float*)d_in[13];
    const float* bfc = (const float*)d_in[14];
    float* out = (float*)d_out;

    const int threads = 512;                     // 16 warps = 16 batch/block
    const int blocks  = BB / (threads / 32);     // 64
    lstm_collapsed_kernel<<<blocks, threads>>>(
        x, Wx0, bx0, bh0, Wx1, bx1, bh1, Wx2, bx2, bh2, Wfc, bfc, out);
}

// round 4
// speedup vs baseline: 1.5039x; 1.2383x over previous
#include <cuda_runtime.h>
#include <cuda_bf16.h>
#include <math.h>

// Problem constants (match reference_code)
#define BB 1024   // batch
#define TT 1024   // time
#define DD 2      // input dim
#define HH 32     // hidden
#define GR 128    // 4*HH gate rows per layer
#define KS 132    // k-stride (floats), 132*4B % 16B == 0 -> LDS.128 aligned, conflict-free

// Proven simplifications:
//  - hx == 0 for every cell call  -> Wh{l} terms vanish; bx+bh fuse
//  - layer 0 has cx == 0          -> c0 = sig(i)*tanh(g)
//  - only rows n = b*T + (T-1) reach the output

__device__ __forceinline__ float fsig(float v) {
    return __fdividef(1.0f, 1.0f + __expf(-v));
}
__device__ __forceinline__ float ftanh(float v) {
    float r; asm("tanh.approx.f32 %0, %1;" : "=f"(r) : "f"(v)); return r;
}

// One dense LSTM layer (hx=0). Weights interleaved-transposed in smem:
// sWt[k*KS + r*4 + g] = W[g*32 + r][k]; lane r reads float4 {i,f,g,o}.
// Bias interleaved: sbt[r*4 + g]. h read from per-warp smem slab (broadcast).
__device__ __forceinline__ void lstm_dense_layer(
    const float* __restrict__ sWt, const float* __restrict__ sbt,
    const float* __restrict__ shwarp, int lane, float& h, float& c)
{
    float4 hv[8];
    #pragma unroll
    for (int j = 0; j < 8; j++)
        hv[j] = *reinterpret_cast<const float4*>(shwarp + 4 * j);   // broadcast

    float4 acc = *reinterpret_cast<const float4*>(sbt + lane * 4);  // {i,f,g,o}

    #pragma unroll
    for (int j = 0; j < 8; j++) {
        #pragma unroll
        for (int t = 0; t < 4; t++) {
            const int k = 4 * j + t;
            const float hk = (t == 0) ? hv[j].x : (t == 1) ? hv[j].y
                           : (t == 2) ? hv[j].z : hv[j].w;
            const float4 w = *reinterpret_cast<const float4*>(sWt + k * KS + lane * 4);
            acc.x = fmaf(w.x, hk, acc.x);
            acc.y = fmaf(w.y, hk, acc.y);
            acc.z = fmaf(w.z, hk, acc.z);
            acc.w = fmaf(w.w, hk, acc.w);
        }
    }
    c = c * fsig(acc.y) + fsig(acc.x) * ftanh(acc.z);
    h = fsig(acc.w) * ftanh(c);
}

__global__ __launch_bounds__(256)
void lstm_collapsed_kernel(
    const float* __restrict__ x,
    const float* __restrict__ Wx0, const float* __restrict__ bx0, const float* __restrict__ bh0,
    const float* __restrict__ Wx1, const float* __restrict__ bx1, const float* __restrict__ bh1,
    const float* __restrict__ Wx2, const float* __restrict__ bx2, const float* __restrict__ bh2,
    const float* __restrict__ Wfc, const float* __restrict__ bfc,
    float* __restrict__ out)
{
    __shared__ float sW1t[HH * KS];          // interleaved-transposed
    __shared__ float sW2t[HH * KS];
    __shared__ float sW0[GR * DD];           // [row][d] row-major
    __shared__ float sb0t[GR], sb1t[GR], sb2t[GR];  // fused bx+bh, interleaved r*4+g
    __shared__ float sWfc[HH];
    __shared__ float sh[8 * HH];             // per-warp h broadcast slabs

    const int tid  = threadIdx.x;
    const int warp = tid >> 5;
    const int lane = tid & 31;
    const int b = blockIdx.x * 8 + warp;     // one warp per batch elem

    // Scattered per-batch x load issued first to hide its latency under staging.
    const float* xr = x + ((size_t)b * TT + (TT - 1)) * DD;
    const float x0 = xr[0];
    const float x1 = xr[1];

    // Stage weights with vectorized LDG.128 (4 per thread per matrix).
    const float4* W1v = reinterpret_cast<const float4*>(Wx1);
    const float4* W2v = reinterpret_cast<const float4*>(Wx2);
    #pragma unroll
    for (int it = 0; it < 4; it++) {
        const int q   = tid + it * 256;      // float4 index, 0..1023
        const float4 v1 = W1v[q];
        const float4 v2 = W2v[q];
        const int row = q >> 3;              // 0..127
        const int g   = row >> 5;            // gate
        const int r   = row & 31;            // unit
        const int k0  = (q & 7) * 4;         // k of v.x
        const int base = r * 4 + g;
        sW1t[(k0 + 0) * KS + base] = v1.x;
        sW1t[(k0 + 1) * KS + base] = v1.y;
        sW1t[(k0 + 2) * KS + base] = v1.z;
        sW1t[(k0 + 3) * KS + base] = v1.w;
        sW2t[(k0 + 0) * KS + base] = v2.x;
        sW2t[(k0 + 1) * KS + base] = v2.y;
        sW2t[(k0 + 2) * KS + base] = v2.z;
        sW2t[(k0 + 3) * KS + base] = v2.w;
    }
    sW0[tid] = Wx0[tid];                     // exactly 256 elements
    if (tid < GR) {
        const int g = tid >> 5, r = tid & 31;
        const int a = r * 4 + g;
        sb0t[a] = bx0[tid] + bh0[tid];
        sb1t[a] = bx1[tid] + bh1[tid];
        sb2t[a] = bx2[tid] + bh2[tid];
    }
    if (tid < HH) sWfc[tid] = Wfc[tid];
    __syncthreads();

    // ---- layer 0: gates = x @ Wx0^T + (bx0+bh0); cx = 0 ----
    const float4 b0 = *reinterpret_cast<const float4*>(sb0t + lane * 4);  // {i,f,g,o}
    const float2 wi = *reinterpret_cast<const float2*>(sW0 + (0 * HH + lane) * DD);
    const float2 wg = *reinterpret_cast<const float2*>(sW0 + (2 * HH + lane) * DD);
    const float2 wo = *reinterpret_cast<const float2*>(sW0 + (3 * HH + lane) * DD);
    const float gi0 = fmaf(wi.y, x1, fmaf(wi.x, x0, b0.x));
    const float gg0 = fmaf(wg.y, x1, fmaf(wg.x, x0, b0.z));
    const float go0 = fmaf(wo.y, x1, fmaf(wo.x, x0, b0.w));
    float c = fsig(gi0) * ftanh(gg0);        // f-gate term vanishes (cx=0)
    float h = fsig(go0) * ftanh(c);

    float* shw = sh + warp * HH;

    // ---- layer 1 ----
    shw[lane] = h;
    __syncwarp();
    lstm_dense_layer(sW1t, sb1t, shw, lane, h, c);

    // ---- layer 2 ----
    __syncwarp();                            // all lanes done reading layer-1 slab
    shw[lane] = h;
    __syncwarp();
    lstm_dense_layer(sW2t, sb2t, shw, lane, h, c);

    // ---- final FC: out[b] = sum_k h[k]*Wfc[k] + bfc ----
    float p = h * sWfc[lane];
    #pragma unroll
    for (int off = 16; off > 0; off >>= 1)
        p += __shfl_down_sync(0xffffffffu, p, off);
    if (lane == 0) out[b] = p + bfc[0];
}

extern "C" void kernel_launch(void* const* d_in, const int* in_sizes, int n_in,
                              void* d_out, int out_size)
{
    // metadata order: x, Wx0,bx0,Wh0,bh0, Wx1,bx1,Wh1,bh1, Wx2,bx2,Wh2,bh2, Wfc,bfc
    const float* x   = (const float*)d_in[0];
    const float* Wx0 = (const float*)d_in[1];
    const float* bx0 = (const float*)d_in[2];
    const float* bh0 = (const float*)d_in[4];   // Wh0 (d_in[3]) unused: hx == 0
    const float* Wx1 = (const float*)d_in[5];
    const float* bx1 = (const float*)d_in[6];
    const float* bh1 = (const float*)d_in[8];   // Wh1 unused
    const float* Wx2 = (const float*)d_in[9];
    const float* bx2 = (const float*)d_in[10];
    const float* bh2 = (const float*)d_in[12];  // Wh2 unused
    const float* Wfc = (const float*)d_in[13];
    const float* bfc = (const float*)d_in[14];
    float* out = (float*)d_out;

    const int threads = 256;                 // 8 warps = 8 batch elems / block
    const int blocks  = BB / 8;              // 128 -> covers 128 SMs
    lstm_collapsed_kernel<<<blocks, threads>>>(
        x, Wx0, bx0, bh0, Wx1, bx1, bh1, Wx2, bx2, bh2, Wfc, bfc, out);
}

// round 5
// speedup vs baseline: 1.5098x; 1.0039x over previous
#include <cuda_runtime.h>
#include <cuda_bf16.h>
#include <math.h>

// Problem constants (match reference_code)
#define BB 1024   // batch
#define TT 1024   // time
#define DD 2      // input dim
#define HH 32     // hidden
#define GR 128    // 4*HH gate rows per layer

// Proven simplifications:
//  - hx == 0 for every cell call  -> Wh{l} terms vanish; bx+bh fuse
//  - layer 0 has cx == 0          -> c0 = sig(i)*tanh(g)
//  - only rows n = b*T + (T-1) reach the output

__device__ __forceinline__ float fsig(float v) {
    return __fdividef(1.0f, 1.0f + __expf(-v));
}
__device__ __forceinline__ float ftanh(float v) {
    float r; asm("tanh.approx.f32 %0, %1;" : "=f"(r) : "f"(v)); return r;
}

// Swizzled 16B index: identity row layout, column block c XOR'd with (row & 7).
// q is the linear float4 index (row = q>>3, c = q&7). Conflict-free for both
// the coalesced staging STS.128 and the per-gate-row column LDS.128.
__device__ __forceinline__ int swz(int q) {
    return (q & ~7) | ((q ^ (q >> 3)) & 7);
}

// One dense LSTM layer (hx=0). sW = swizzled row-major [128 x 32] float4 view.
// Bias values arrive in registers (loaded from gmem at kernel start).
__device__ __forceinline__ void lstm_dense_layer(
    const float4* __restrict__ sW, const float* __restrict__ shwarp,
    float bi, float bf, float bg, float bo, int lane, float& h, float& c)
{
    float4 hv[8];
    #pragma unroll
    for (int j = 0; j < 8; j++)
        hv[j] = *reinterpret_cast<const float4*>(shwarp + 4 * j);   // broadcast

    float ai = bi, af = bf, ag = bg, ao = bo;
    const int lx = lane & 7;

    #pragma unroll
    for (int j = 0; j < 8; j++) {
        const int jc = j ^ lx;                       // swizzled column block
        const float4 wi = sW[(0 * HH + lane) * 8 + jc];
        const float4 wf = sW[(1 * HH + lane) * 8 + jc];
        const float4 wg = sW[(2 * HH + lane) * 8 + jc];
        const float4 wo = sW[(3 * HH + lane) * 8 + jc];
        const float4 hj = hv[j];
        ai = fmaf(wi.x, hj.x, ai); ai = fmaf(wi.y, hj.y, ai);
        ai = fmaf(wi.z, hj.z, ai); ai = fmaf(wi.w, hj.w, ai);
        af = fmaf(wf.x, hj.x, af); af = fmaf(wf.y, hj.y, af);
        af = fmaf(wf.z, hj.z, af); af = fmaf(wf.w, hj.w, af);
        ag = fmaf(wg.x, hj.x, ag); ag = fmaf(wg.y, hj.y, ag);
        ag = fmaf(wg.z, hj.z, ag); ag = fmaf(wg.w, hj.w, ag);
        ao = fmaf(wo.x, hj.x, ao); ao = fmaf(wo.y, hj.y, ao);
        ao = fmaf(wo.z, hj.z, ao); ao = fmaf(wo.w, hj.w, ao);
    }
    c = c * fsig(af) + fsig(ai) * ftanh(ag);
    h = fsig(ao) * ftanh(c);
}

__global__ __launch_bounds__(256)
void lstm_collapsed_kernel(
    const float* __restrict__ x,
    const float* __restrict__ Wx0, const float* __restrict__ bx0, const float* __restrict__ bh0,
    const float* __restrict__ Wx1, const float* __restrict__ bx1, const float* __restrict__ bh1,
    const float* __restrict__ Wx2, const float* __restrict__ bx2, const float* __restrict__ bh2,
    const float* __restrict__ Wfc, const float* __restrict__ bfc,
    float* __restrict__ out)
{
    __shared__ float4 sW1[GR * 8];           // 16 KB, swizzled identity copy
    __shared__ float4 sW2[GR * 8];           // 16 KB
    __shared__ float  sh[8 * HH];            // per-warp h broadcast slabs

    const int tid  = threadIdx.x;
    const int warp = tid >> 5;
    const int lane = tid & 31;
    const int b = blockIdx.x * 8 + warp;     // one warp per batch elem

    // --- Issue ALL small per-lane gmem loads first; latency hides under staging ---
    const float* xr = x + ((size_t)b * TT + (TT - 1)) * DD;
    const float x0v = xr[0];
    const float x1v = xr[1];

    // layer-0 weights/biases (only i,g,o rows matter; f vanishes with cx=0)
    const float2 w0i = *reinterpret_cast<const float2*>(Wx0 + (0 * HH + lane) * DD);
    const float2 w0g = *reinterpret_cast<const float2*>(Wx0 + (2 * HH + lane) * DD);
    const float2 w0o = *reinterpret_cast<const float2*>(Wx0 + (3 * HH + lane) * DD);
    const float b0i = bx0[0 * HH + lane] + bh0[0 * HH + lane];
    const float b0g = bx0[2 * HH + lane] + bh0[2 * HH + lane];
    const float b0o = bx0[3 * HH + lane] + bh0[3 * HH + lane];

    const float b1i = bx1[0 * HH + lane] + bh1[0 * HH + lane];
    const float b1f = bx1[1 * HH + lane] + bh1[1 * HH + lane];
    const float b1g = bx1[2 * HH + lane] + bh1[2 * HH + lane];
    const float b1o = bx1[3 * HH + lane] + bh1[3 * HH + lane];

    const float b2i = bx2[0 * HH + lane] + bh2[0 * HH + lane];
    const float b2f = bx2[1 * HH + lane] + bh2[1 * HH + lane];
    const float b2g = bx2[2 * HH + lane] + bh2[2 * HH + lane];
    const float b2o = bx2[3 * HH + lane] + bh2[3 * HH + lane];

    const float wfc = Wfc[lane];
    const float bfcv = bfc[0];

    // --- Stage big matrices: identity copy with XOR swizzle (no transpose) ---
    const float4* W1v = reinterpret_cast<const float4*>(Wx1);
    const float4* W2v = reinterpret_cast<const float4*>(Wx2);
    #pragma unroll
    for (int it = 0; it < 4; it++) {
        const int q  = tid + it * 256;       // 0..1023
        const int sq = swz(q);
        sW1[sq] = W1v[q];
        sW2[sq] = W2v[q];
    }

    // ---- layer 0 (pure registers, no smem dependency) ----
    const float gi0 = fmaf(w0i.y, x1v, fmaf(w0i.x, x0v, b0i));
    const float gg0 = fmaf(w0g.y, x1v, fmaf(w0g.x, x0v, b0g));
    const float go0 = fmaf(w0o.y, x1v, fmaf(w0o.x, x0v, b0o));
    float c = fsig(gi0) * ftanh(gg0);        // f-gate term vanishes (cx=0)
    float h = fsig(go0) * ftanh(c);

    float* shw = sh + warp * HH;
    shw[lane] = h;                           // publish before block barrier
    __syncthreads();                         // sW1/sW2 (and shw) ready

    // ---- layer 1 ----
    lstm_dense_layer(sW1, shw, b1i, b1f, b1g, b1o, lane, h, c);

    // ---- layer 2 ----
    __syncwarp();
    shw[lane] = h;
    __syncwarp();
    lstm_dense_layer(sW2, shw, b2i, b2f, b2g, b2o, lane, h, c);

    // ---- final FC: out[b] = sum_k h[k]*Wfc[k] + bfc ----
    float p = h * wfc;
    #pragma unroll
    for (int off = 16; off > 0; off >>= 1)
        p += __shfl_down_sync(0xffffffffu, p, off);
    if (lane == 0) out[b] = p + bfcv;
}

extern "C" void kernel_launch(void* const* d_in, const int* in_sizes, int n_in,
                              void* d_out, int out_size)
{
    // metadata order: x, Wx0,bx0,Wh0,bh0, Wx1,bx1,Wh1,bh1, Wx2,bx2,Wh2,bh2, Wfc,bfc
    const float* x   = (const float*)d_in[0];
    const float* Wx0 = (const float*)d_in[1];
    const float* bx0 = (const float*)d_in[2];
    const float* bh0 = (const float*)d_in[4];   // Wh0 (d_in[3]) unused: hx == 0
    const float* Wx1 = (const float*)d_in[5];
    const float* bx1 = (const float*)d_in[6];
    const float* bh1 = (const float*)d_in[8];   // Wh1 unused
    const float* Wx2 = (const float*)d_in[9];
    const float* bx2 = (const float*)d_in[10];
    const float* bh2 = (const float*)d_in[12];  // Wh2 unused
    const float* Wfc = (const float*)d_in[13];
    const float* bfc = (const float*)d_in[14];
    float* out = (float*)d_out;

    const int threads = 256;                 // 8 warps = 8 batch elems / block
    const int blocks  = BB / 8;              // 128 blocks -> ~all SMs get one
    lstm_collapsed_kernel<<<blocks, threads>>>(
        x, Wx0, bx0, bh0, Wx1, bx1, bh1, Wx2, bx2, bh2, Wfc, bfc, out);
}